// round 12
// baseline (speedup 1.0000x reference)
#include <cuda_runtime.h>

#define BB 4
#define TT 1024
#define CHN 4
#define FF 481
#define KK 48
#define NC 16
#define NTHR 512
#define NFG 5
#define CHUNK 97
#define KCN (KK * NC)  // 768

// scratch: band-cov intermediate, (b,t,k,c) complex — scanned in place
__device__ float2 g_bc[BB * TT * KK * NC];  // 25.2 MB

__device__ __forceinline__ unsigned long long fma2(unsigned long long a,
                                                   unsigned long long b,
                                                   unsigned long long c) {
    unsigned long long d;
    asm("fma.rn.f32x2 %0, %1, %2, %3;" : "=l"(d) : "l"(a), "l"(b), "l"(c));
    return d;
}
__device__ __forceinline__ unsigned long long pack2(float lo, float hi) {
    unsigned long long r;
    asm("mov.b64 %0, {%1, %2};" : "=l"(r) : "f"(lo), "f"(hi));
    return r;
}
__device__ __forceinline__ void unpack2(unsigned long long v, float& lo, float& hi) {
    asm("mov.b64 {%0, %1}, %2;" : "=f"(lo), "=f"(hi) : "l"(v));
}
__device__ __forceinline__ void lds128(unsigned addr, unsigned long long& a,
                                       unsigned long long& b) {
    asm volatile("ld.shared.v2.u64 {%0, %1}, [%2];" : "=l"(a), "=l"(b) : "r"(addr));
}

// ---------------------------------------------------------------------------
// Kernel 1: per (b,t): cov -> phase-adjust -> band GEMM -> diag-normalize
// 2 CTAs/SM: regs capped at 63 via launch_bounds; each phase-4 thread owns
// half the c-elements (8 complex accumulators = 16 regs).
// ---------------------------------------------------------------------------
__global__ void __launch_bounds__(NTHR, 2) band_cov_kernel(
    const float* __restrict__ binr, const float* __restrict__ bini,
    const float* __restrict__ bandr, const float* __restrict__ bandi) {
    extern __shared__ float sm[];
    float* s_x = sm;                 // FF*8 = 3848
    float* s_pw = s_x + FF * 8;      // 512
    float* s_ax = s_pw + 512;        // FF*NC = 7696
    float* s_ay = s_ax + FF * NC;    // 7696

    const int bt = blockIdx.x;
    const int tid = threadIdx.x;

    // --- phase 1: load x tile into f-major float2 layout ---
    {
        const float* br_ = binr + (size_t)bt * CHN * FF;
        const float* bi_ = bini + (size_t)bt * CHN * FF;
        for (int i = tid; i < CHN * FF; i += NTHR) {
            int ch = i / FF;
            int f = i - ch * FF;
            s_x[f * 8 + ch * 2] = br_[i];
            s_x[f * 8 + ch * 2 + 1] = bi_[i];
        }
    }
    __syncthreads();

    // --- phase 1b: inverse trace per bin ---
    for (int f = tid; f < FF; f += NTHR) {
        float pw = 0.f;
#pragma unroll
        for (int ch = 0; ch < CHN; ch++) {
            float r = s_x[f * 8 + 2 * ch];
            float m = s_x[f * 8 + 2 * ch + 1];
            pw += r * r + m * m;
        }
        s_pw[f] = 1.0f / fmaxf(pw, 1e-20f);
    }
    __syncthreads();

    // --- phase 2+3 fused: adj[f][c] directly (uniform formula, no branch) ---
    {
        const float2* x2 = (const float2*)s_x;  // x2[f*4 + ch]
        for (int idx = tid; idx < FF * NC; idx += NTHR) {
            int f = idx >> 4;
            int c = idx & 15;
            int i = c >> 2, j = c & 3;
            int fm = (f == 0) ? 0 : ((f == FF - 1) ? FF - 3 : f - 1);
            int fp = (f == 0) ? 2 : ((f == FF - 1) ? FF - 1 : f + 1);

            float2 aF = x2[f * 4 + i], bF = x2[f * 4 + j];
            float2 aM = x2[fm * 4 + i], bM = x2[fm * 4 + j];
            float2 aP = x2[fp * 4 + i], bP = x2[fp * 4 + j];

            float crF = aF.x * bF.x + aF.y * bF.y;
            float ciF = aF.y * bF.x - aF.x * bF.y;
            float crM = aM.x * bM.x + aM.y * bM.y;
            float ciM = aM.y * bM.x - aM.x * bM.y;
            float crP = aP.x * bP.x + aP.y * bP.y;
            float ciP = aP.y * bP.x - aP.x * bP.y;

            float zr = crM * crP + ciM * ciP;
            float zi = crM * ciP - ciM * crP;
            float zl2 = zr * zr + zi * zi;

            float m = sqrtf(crF * crF + ciF * ciF) * s_pw[f];

            float ax, ay;
            if (zl2 > 0.f) {
                float s = m * rsqrtf(zl2);
                ax = s * zr;
                ay = s * zi;
            } else {
                ax = m;
                ay = 0.f;
            }
            s_ax[idx] = ax;
            s_ay[idx] = ay;
        }
    }
    __syncthreads();

    // --- phase 4: bc[k][c] += adj[f][c]*band[f][k]; thread = (fg, half, k) ---
    const bool act = tid < NFG * 2 * KK;  // 480
    unsigned long long accX[4], accY[4];
#pragma unroll
    for (int p = 0; p < 4; p++) {
        accX[p] = 0ull;
        accY[p] = 0ull;
    }
    if (act) {
        const int fg = tid / 96;
        const int rr = tid - fg * 96;
        const int half = rr / KK;
        const int k = rr - half * KK;
        const int f0 = fg * CHUNK;
        const int f1 = (f0 + CHUNK < FF) ? f0 + CHUNK : FF;
        unsigned axbase =
            (unsigned)__cvta_generic_to_shared(s_ax) + half * 32;
        unsigned aybase =
            (unsigned)__cvta_generic_to_shared(s_ay) + half * 32;
        float brn = bandr[f0 * KK + k];
        float bin_ = bandi[f0 * KK + k];
        for (int f = f0; f < f1; f++) {
            float brv = brn, biv = bin_;
            if (f + 1 < f1) {  // prefetch next band coefficient
                brn = bandr[(f + 1) * KK + k];
                bin_ = bandi[(f + 1) * KK + k];
            }
            unsigned long long brbr = pack2(brv, brv);
            unsigned long long bibi = pack2(biv, biv);
            unsigned long long nbnb = pack2(-biv, -biv);
            unsigned axa = axbase + f * 64;
            unsigned aya = aybase + f * 64;
#pragma unroll
            for (int q = 0; q < 2; q++) {
                unsigned long long ax0, ax1, ay0, ay1;
                lds128(axa + q * 16, ax0, ax1);
                lds128(aya + q * 16, ay0, ay1);
                int p = 2 * q;
                accX[p] = fma2(ax0, brbr, accX[p]);
                accX[p] = fma2(ay0, nbnb, accX[p]);
                accY[p] = fma2(ax0, bibi, accY[p]);
                accY[p] = fma2(ay0, brbr, accY[p]);
                accX[p + 1] = fma2(ax1, brbr, accX[p + 1]);
                accX[p + 1] = fma2(ay1, nbnb, accX[p + 1]);
                accY[p + 1] = fma2(ax1, bibi, accY[p + 1]);
                accY[p + 1] = fma2(ay1, brbr, accY[p + 1]);
            }
        }
    }
    __syncthreads();  // all adj reads complete; planes now reusable

    // --- partial store, SoA: part[c][fg*48+k] ---
    if (act) {
        const int fg = tid / 96;
        const int rr = tid - fg * 96;
        const int half = rr / KK;
        const int k = rr - half * KK;
        const int fgk = fg * KK + k;
#pragma unroll
        for (int j = 0; j < 4; j++) {
            int c0 = half * 8 + 2 * j;
            float lo, hi;
            unpack2(accX[j], lo, hi);
            s_ax[c0 * (NFG * KK) + fgk] = lo;
            s_ax[(c0 + 1) * (NFG * KK) + fgk] = hi;
            unpack2(accY[j], lo, hi);
            s_ay[c0 * (NFG * KK) + fgk] = lo;
            s_ay[(c0 + 1) * (NFG * KK) + fgk] = hi;
        }
    }
    __syncthreads();

    // --- reduce over fg, stage SoA: stage[c*48+k] ---
    for (int r = tid; r < KK * NC; r += NTHR) {
        int e = r / KK;
        int k = r - e * KK;
        float sx = 0.f, sy = 0.f;
#pragma unroll
        for (int fg = 0; fg < NFG; fg++) {
            sx += s_ax[e * (NFG * KK) + fg * KK + k];
            sy += s_ay[e * (NFG * KK) + fg * KK + k];
        }
        s_x[e * KK + k] = sx;
        s_x[KK * NC + e * KK + k] = sy;
    }
    __syncthreads();

    // --- normalize by clipped diagonal sum, write (b,t,k,c) ---
    for (int r = tid; r < KK * NC; r += NTHR) {
        int c = r / KK;
        int k = r - c * KK;
        float ds = s_x[0 * KK + k] + s_x[5 * KK + k] + s_x[10 * KK + k] +
                   s_x[15 * KK + k];
        float inv = 1.0f / fmaxf(ds, 1e-20f);
        g_bc[(size_t)bt * (KK * NC) + k * NC + c] =
            make_float2(s_x[c * KK + k] * inv, s_x[KK * NC + c * KK + k] * inv);
    }
}

// ---------------------------------------------------------------------------
// Kernel 2: serial IIR scan, one warp per 32 contiguous (k,c) chains.
// Fully coalesced 256B per warp access, 2 passes total (read + write).
// ---------------------------------------------------------------------------
__global__ void __launch_bounds__(32) scan_kernel(const float* __restrict__ tau) {
    const int w = blockIdx.x;              // 96 warps total
    const int lane = threadIdx.x;
    const int WPB = KCN / 32;              // 24 warps per batch
    const int b = w / WPB;                 // 0..3  (FIXED: was /3)
    const int kc = (w - b * WPB) * 32 + lane;  // contiguous chains 0..767
    const int k = kc >> 4;

    const float a = expf(-10.0f / tau[k]);
    const float om = 1.0f - a;
    const unsigned long long aa = pack2(a, a);
    const unsigned long long oo = pack2(om, om);

    unsigned long long* q =
        (unsigned long long*)g_bc + (size_t)b * TT * KCN + kc;

    unsigned long long y = q[0];          // y_0 = x_0, already in place
    unsigned long long x = q[KCN];        // prefetch t=1
#pragma unroll 4
    for (int t = 1; t < TT; t++) {
        unsigned long long xn = 0ull;
        if (t + 1 < TT) xn = q[(size_t)(t + 1) * KCN];
        y = fma2(aa, y, fma2(oo, x, 0ull));
        q[(size_t)t * KCN] = y;
        x = xn;
    }
}

// ---------------------------------------------------------------------------
// Kernel 3: pv[b,k,t,p] = Re( c2pv[p,:] . y[b,t,k,:] )
// ---------------------------------------------------------------------------
__global__ void __launch_bounds__(256) proj_kernel(const float* __restrict__ pr,
                                                   const float* __restrict__ pi,
                                                   float* __restrict__ out) {
    __shared__ float cr[256], ci[256];  // transposed: [c][p]
    int tid = threadIdx.x;
    {
        int c = tid >> 4, p = tid & 15;
        cr[c * 16 + p] = pr[p * 16 + c];
        ci[c * 16 + p] = pi[p * 16 + c];
    }
    __syncthreads();

    int g = blockIdx.x * 16 + (tid >> 4);  // flat (b,k,t) in output order
    int p = tid & 15;
    int t = g % TT;
    int bk = g / TT;
    int b = bk / KK, k = bk % KK;

    size_t ybase = (((size_t)b * TT + t) * KK + k) * NC;
    float s = 0.f;
#pragma unroll
    for (int c = 0; c < NC; c++) {
        float2 y = g_bc[ybase + c];
        s = fmaf(cr[c * 16 + p], y.x, s);
        s = fmaf(-ci[c * 16 + p], y.y, s);
    }
    out[(size_t)g * 16 + p] = s;
}

// ---------------------------------------------------------------------------
extern "C" void kernel_launch(void* const* d_in, const int* in_sizes, int n_in,
                              void* d_out, int out_size) {
    const float* binr = (const float*)d_in[0];
    const float* bini = (const float*)d_in[1];
    const float* bandr = (const float*)d_in[2];
    const float* bandi = (const float*)d_in[3];
    const float* pr = (const float*)d_in[4];
    const float* pi = (const float*)d_in[5];
    const float* tau = (const float*)d_in[6];
    float* out = (float*)d_out;

    const int smem = (FF * 8 + 512 + 2 * FF * NC) * (int)sizeof(float);  // 79008 B
    cudaFuncSetAttribute(band_cov_kernel,
                         cudaFuncAttributeMaxDynamicSharedMemorySize, smem);

    band_cov_kernel<<<BB * TT, NTHR, smem>>>(binr, bini, bandr, bandi);
    scan_kernel<<<BB * KCN / 32, 32>>>(tau);
    proj_kernel<<<BB * KK * TT / 16, 256>>>(pr, pi, out);
}

// round 15
// speedup vs baseline: 1.3198x; 1.3198x over previous
#include <cuda_runtime.h>

#define BB 4
#define TT 1024
#define CHN 4
#define FF 481
#define KK 48
#define NC 16
#define NTHR 512
#define NFG 5
#define CHUNK 97
#define KCN (KK * NC)  // 768
#define NSEG 16
#define SEGT (TT / NSEG)  // 64

// scratch: band-cov intermediate, (b,t,k,c) complex — scanned in place
__device__ float2 g_bc[BB * TT * KK * NC];  // 25.2 MB

__device__ __forceinline__ unsigned long long fma2(unsigned long long a,
                                                   unsigned long long b,
                                                   unsigned long long c) {
    unsigned long long d;
    asm("fma.rn.f32x2 %0, %1, %2, %3;" : "=l"(d) : "l"(a), "l"(b), "l"(c));
    return d;
}
__device__ __forceinline__ unsigned long long pack2(float lo, float hi) {
    unsigned long long r;
    asm("mov.b64 %0, {%1, %2};" : "=l"(r) : "f"(lo), "f"(hi));
    return r;
}
__device__ __forceinline__ void unpack2(unsigned long long v, float& lo, float& hi) {
    asm("mov.b64 {%0, %1}, %2;" : "=f"(lo), "=f"(hi) : "l"(v));
}
__device__ __forceinline__ void lds128(unsigned addr, unsigned long long& a,
                                       unsigned long long& b) {
    asm volatile("ld.shared.v2.u64 {%0, %1}, [%2];" : "=l"(a), "=l"(b) : "r"(addr));
}

// ---------------------------------------------------------------------------
// Kernel 1: per (b,t): cov -> phase-adjust -> band GEMM -> diag-normalize
// 2 CTAs/SM: regs capped at 64; phase-4 thread owns half the c-elements.
// ---------------------------------------------------------------------------
__global__ void __launch_bounds__(NTHR, 2) band_cov_kernel(
    const float* __restrict__ binr, const float* __restrict__ bini,
    const float* __restrict__ bandr, const float* __restrict__ bandi) {
    extern __shared__ float sm[];
    float* s_x = sm;                 // FF*8 = 3848
    float* s_pw = s_x + FF * 8;      // 512
    float* s_ax = s_pw + 512;        // FF*NC = 7696
    float* s_ay = s_ax + FF * NC;    // 7696

    const int bt = blockIdx.x;
    const int tid = threadIdx.x;

    // --- phase 1: load x tile into f-major float2 layout ---
    {
        const float* br_ = binr + (size_t)bt * CHN * FF;
        const float* bi_ = bini + (size_t)bt * CHN * FF;
        for (int i = tid; i < CHN * FF; i += NTHR) {
            int ch = i / FF;
            int f = i - ch * FF;
            s_x[f * 8 + ch * 2] = br_[i];
            s_x[f * 8 + ch * 2 + 1] = bi_[i];
        }
    }
    __syncthreads();

    // --- phase 1b: inverse trace per bin ---
    for (int f = tid; f < FF; f += NTHR) {
        float pw = 0.f;
#pragma unroll
        for (int ch = 0; ch < CHN; ch++) {
            float r = s_x[f * 8 + 2 * ch];
            float m = s_x[f * 8 + 2 * ch + 1];
            pw += r * r + m * m;
        }
        s_pw[f] = 1.0f / fmaxf(pw, 1e-20f);
    }
    __syncthreads();

    // --- phase 2+3 fused: adj[f][c] directly (uniform formula, no branch) ---
    {
        const float2* x2 = (const float2*)s_x;  // x2[f*4 + ch]
        for (int idx = tid; idx < FF * NC; idx += NTHR) {
            int f = idx >> 4;
            int c = idx & 15;
            int i = c >> 2, j = c & 3;
            int fm = (f == 0) ? 0 : ((f == FF - 1) ? FF - 3 : f - 1);
            int fp = (f == 0) ? 2 : ((f == FF - 1) ? FF - 1 : f + 1);

            float2 aF = x2[f * 4 + i], bF = x2[f * 4 + j];
            float2 aM = x2[fm * 4 + i], bM = x2[fm * 4 + j];
            float2 aP = x2[fp * 4 + i], bP = x2[fp * 4 + j];

            float crF = aF.x * bF.x + aF.y * bF.y;
            float ciF = aF.y * bF.x - aF.x * bF.y;
            float crM = aM.x * bM.x + aM.y * bM.y;
            float ciM = aM.y * bM.x - aM.x * bM.y;
            float crP = aP.x * bP.x + aP.y * bP.y;
            float ciP = aP.y * bP.x - aP.x * bP.y;

            float zr = crM * crP + ciM * ciP;
            float zi = crM * ciP - ciM * crP;
            float zl2 = zr * zr + zi * zi;

            float m = sqrtf(crF * crF + ciF * ciF) * s_pw[f];

            float ax, ay;
            if (zl2 > 0.f) {
                float s = m * rsqrtf(zl2);
                ax = s * zr;
                ay = s * zi;
            } else {
                ax = m;
                ay = 0.f;
            }
            s_ax[idx] = ax;
            s_ay[idx] = ay;
        }
    }
    __syncthreads();

    // --- phase 4: bc[k][c] += adj[f][c]*band[f][k]; thread = (fg, half, k) ---
    const bool act = tid < NFG * 2 * KK;  // 480
    unsigned long long accX[4], accY[4];
#pragma unroll
    for (int p = 0; p < 4; p++) {
        accX[p] = 0ull;
        accY[p] = 0ull;
    }
    if (act) {
        const int fg = tid / 96;
        const int rr = tid - fg * 96;
        const int half = rr / KK;
        const int k = rr - half * KK;
        const int f0 = fg * CHUNK;
        const int f1 = (f0 + CHUNK < FF) ? f0 + CHUNK : FF;
        unsigned axbase =
            (unsigned)__cvta_generic_to_shared(s_ax) + half * 32;
        unsigned aybase =
            (unsigned)__cvta_generic_to_shared(s_ay) + half * 32;
        float brn = bandr[f0 * KK + k];
        float bin_ = bandi[f0 * KK + k];
        for (int f = f0; f < f1; f++) {
            float brv = brn, biv = bin_;
            if (f + 1 < f1) {  // prefetch next band coefficient
                brn = bandr[(f + 1) * KK + k];
                bin_ = bandi[(f + 1) * KK + k];
            }
            unsigned long long brbr = pack2(brv, brv);
            unsigned long long bibi = pack2(biv, biv);
            unsigned long long nbnb = pack2(-biv, -biv);
            unsigned axa = axbase + f * 64;
            unsigned aya = aybase + f * 64;
#pragma unroll
            for (int q = 0; q < 2; q++) {
                unsigned long long ax0, ax1, ay0, ay1;
                lds128(axa + q * 16, ax0, ax1);
                lds128(aya + q * 16, ay0, ay1);
                int p = 2 * q;
                accX[p] = fma2(ax0, brbr, accX[p]);
                accX[p] = fma2(ay0, nbnb, accX[p]);
                accY[p] = fma2(ax0, bibi, accY[p]);
                accY[p] = fma2(ay0, brbr, accY[p]);
                accX[p + 1] = fma2(ax1, brbr, accX[p + 1]);
                accX[p + 1] = fma2(ay1, nbnb, accX[p + 1]);
                accY[p + 1] = fma2(ax1, bibi, accY[p + 1]);
                accY[p + 1] = fma2(ay1, brbr, accY[p + 1]);
            }
        }
    }
    __syncthreads();  // all adj reads complete; planes now reusable

    // --- partial store, SoA: part[c][fg*48+k] ---
    if (act) {
        const int fg = tid / 96;
        const int rr = tid - fg * 96;
        const int half = rr / KK;
        const int k = rr - half * KK;
        const int fgk = fg * KK + k;
#pragma unroll
        for (int j = 0; j < 4; j++) {
            int c0 = half * 8 + 2 * j;
            float lo, hi;
            unpack2(accX[j], lo, hi);
            s_ax[c0 * (NFG * KK) + fgk] = lo;
            s_ax[(c0 + 1) * (NFG * KK) + fgk] = hi;
            unpack2(accY[j], lo, hi);
            s_ay[c0 * (NFG * KK) + fgk] = lo;
            s_ay[(c0 + 1) * (NFG * KK) + fgk] = hi;
        }
    }
    __syncthreads();

    // --- reduce over fg, stage SoA: stage[c*48+k] ---
    for (int r = tid; r < KK * NC; r += NTHR) {
        int e = r / KK;
        int k = r - e * KK;
        float sx = 0.f, sy = 0.f;
#pragma unroll
        for (int fg = 0; fg < NFG; fg++) {
            sx += s_ax[e * (NFG * KK) + fg * KK + k];
            sy += s_ay[e * (NFG * KK) + fg * KK + k];
        }
        s_x[e * KK + k] = sx;
        s_x[KK * NC + e * KK + k] = sy;
    }
    __syncthreads();

    // --- normalize by clipped diagonal sum, write (b,t,k,c) ---
    for (int r = tid; r < KK * NC; r += NTHR) {
        int c = r / KK;
        int k = r - c * KK;
        float ds = s_x[0 * KK + k] + s_x[5 * KK + k] + s_x[10 * KK + k] +
                   s_x[15 * KK + k];
        float inv = 1.0f / fmaxf(ds, 1e-20f);
        g_bc[(size_t)bt * (KK * NC) + k * NC + c] =
            make_float2(s_x[c * KK + k] * inv, s_x[KK * NC + c * KK + k] * inv);
    }
}

// ---------------------------------------------------------------------------
// Kernel 2: block-segmented IIR scan.
// Block = (b, 32-contiguous-kc tile); 16 warps = 16 time segments of 64.
// Lanes = contiguous kc -> coalesced; 4-deep prefetch ring for MLP.
// ---------------------------------------------------------------------------
__global__ void __launch_bounds__(NSEG * 32) scan_kernel(
    const float* __restrict__ tau) {
    __shared__ float s_vx[NSEG][32], s_vy[NSEG][32];
    __shared__ float s_cx[NSEG][32], s_cy[NSEG][32];

    const int lane = threadIdx.x & 31;
    const int w = threadIdx.x >> 5;  // segment id
    const int tile = blockIdx.x % (KCN / 32);
    const int b = blockIdx.x / (KCN / 32);
    const int kc = tile * 32 + lane;
    const int k = kc >> 4;

    const float a = expf(-10.0f / tau[k]);
    const float om = 1.0f - a;
    const unsigned long long aa = pack2(a, a);
    const unsigned long long oo = pack2(om, om);
    float aseg = a;  // a^SEGT
#pragma unroll
    for (int s = 0; s < 6; s++) aseg *= aseg;  // 2^6 = 64 = SEGT

    unsigned long long* q =
        (unsigned long long*)g_bc + (size_t)b * TT * KCN + kc;
    const int t0 = w * SEGT;

    // --- pass A: local scan, zero carry-in (w>0) / exact init (w==0) ---
    unsigned long long xbuf[4];
#pragma unroll
    for (int j = 0; j < 4; j++) xbuf[j] = q[(size_t)(t0 + j) * KCN];

    unsigned long long y;
    if (w == 0) {
        y = xbuf[0];  // y_0 = x_0
    } else {
        y = fma2(oo, xbuf[0], 0ull);
    }
    xbuf[0] = q[(size_t)(t0 + 4) * KCN];
#pragma unroll 4
    for (int j = 1; j < SEGT; j++) {
        unsigned long long x = xbuf[j & 3];
        if (j + 4 < SEGT) xbuf[j & 3] = q[(size_t)(t0 + j + 4) * KCN];
        y = fma2(aa, y, fma2(oo, x, 0ull));
    }
    {
        float lo, hi;
        unpack2(y, lo, hi);
        s_vx[w][lane] = lo;
        s_vy[w][lane] = hi;
    }
    __syncthreads();

    // --- compose carries: C[s] = v[s-1] + a^SEGT * C[s-1], C[1] = v[0] ---
    if (w == 0) {
        float cx = s_vx[0][lane], cy = s_vy[0][lane];  // exact end of seg 0
        s_cx[1][lane] = cx;
        s_cy[1][lane] = cy;
#pragma unroll
        for (int s = 2; s < NSEG; s++) {
            cx = s_vx[s - 1][lane] + aseg * cx;
            cy = s_vy[s - 1][lane] + aseg * cy;
            s_cx[s][lane] = cx;
            s_cy[s][lane] = cy;
        }
    }
    __syncthreads();

    // --- pass B: replay with true carry-in, store ---
#pragma unroll
    for (int j = 0; j < 4; j++) xbuf[j] = q[(size_t)(t0 + j) * KCN];

    if (w == 0) {
        y = xbuf[0];  // t=0 value already in place, no store needed
    } else {
        unsigned long long cin = pack2(s_cx[w][lane], s_cy[w][lane]);
        y = fma2(aa, cin, fma2(oo, xbuf[0], 0ull));
        q[(size_t)t0 * KCN] = y;
    }
    xbuf[0] = q[(size_t)(t0 + 4) * KCN];
#pragma unroll 4
    for (int j = 1; j < SEGT; j++) {
        unsigned long long x = xbuf[j & 3];
        if (j + 4 < SEGT) xbuf[j & 3] = q[(size_t)(t0 + j + 4) * KCN];
        y = fma2(aa, y, fma2(oo, x, 0ull));
        q[(size_t)(t0 + j) * KCN] = y;
    }
}

// ---------------------------------------------------------------------------
// Kernel 3: pv[b,k,t,p] = Re( c2pv[p,:] . y[b,t,k,:] )
// ---------------------------------------------------------------------------
__global__ void __launch_bounds__(256) proj_kernel(const float* __restrict__ pr,
                                                   const float* __restrict__ pi,
                                                   float* __restrict__ out) {
    __shared__ float cr[256], ci[256];  // transposed: [c][p]
    int tid = threadIdx.x;
    {
        int c = tid >> 4, p = tid & 15;
        cr[c * 16 + p] = pr[p * 16 + c];
        ci[c * 16 + p] = pi[p * 16 + c];
    }
    __syncthreads();

    int g = blockIdx.x * 16 + (tid >> 4);  // flat (b,k,t) in output order
    int p = tid & 15;
    int t = g % TT;
    int bk = g / TT;
    int b = bk / KK, k = bk % KK;

    size_t ybase = (((size_t)b * TT + t) * KK + k) * NC;
    float s = 0.f;
#pragma unroll
    for (int c = 0; c < NC; c++) {
        float2 y = g_bc[ybase + c];
        s = fmaf(cr[c * 16 + p], y.x, s);
        s = fmaf(-ci[c * 16 + p], y.y, s);
    }
    out[(size_t)g * 16 + p] = s;
}

// ---------------------------------------------------------------------------
extern "C" void kernel_launch(void* const* d_in, const int* in_sizes, int n_in,
                              void* d_out, int out_size) {
    const float* binr = (const float*)d_in[0];
    const float* bini = (const float*)d_in[1];
    const float* bandr = (const float*)d_in[2];
    const float* bandi = (const float*)d_in[3];
    const float* pr = (const float*)d_in[4];
    const float* pi = (const float*)d_in[5];
    const float* tau = (const float*)d_in[6];
    float* out = (float*)d_out;

    const int smem = (FF * 8 + 512 + 2 * FF * NC) * (int)sizeof(float);  // 79008 B
    cudaFuncSetAttribute(band_cov_kernel,
                         cudaFuncAttributeMaxDynamicSharedMemorySize, smem);

    band_cov_kernel<<<BB * TT, NTHR, smem>>>(binr, bini, bandr, bandi);
    scan_kernel<<<BB * (KCN / 32), NSEG * 32>>>(tau);
    proj_kernel<<<BB * KK * TT / 16, 256>>>(pr, pi, out);
}